// round 14
// baseline (speedup 1.0000x reference)
#include <cuda_runtime.h>

#define Bc  32
#define Nc  128
#define Tc  96
#define Hc  64
#define TFc 24
#define TSLICE 12
#define NSL  8

// Cross-kernel scratch: per-slice GRU-gate partials and softmax normalizers.
__device__ float g_gp[Bc * NSL * 3 * Hc];  // W_ih @ P_slice   (192 per slice)
__device__ float g_Se[Bc * NSL];           // sum_t e^att[t]   (per slice)

// 2*log2(e): folded into ODE weights so tanh needs no pre-multiply.
#define TANH_SCALE 2.8853900817779268f

// Overflow-safe fast tanh: 1 - 2/(e^{2x}+1)  (front/GRU path, unscaled input)
__device__ __forceinline__ float ftanh(float x) {
    float e = __expf(2.0f * x);
    return 1.0f - __fdividef(2.0f, e + 1.0f);
}
__device__ __forceinline__ float fsigm(float x) {
    return __fdividef(1.0f, 1.0f + __expf(-x));
}

// ODE-path tanh from pre-scaled dot z = 2*log2e*(w.v+b): tanh = 1 - 2*rcp(2^z+1).
__device__ __forceinline__ float ftanh_z(float z) {
    float e, r;
    asm("ex2.approx.f32 %0, %1;" : "=f"(e) : "f"(z));
    asm("rcp.approx.f32 %0, %1;" : "=f"(r) : "f"(e + 1.0f));
    return fmaf(-2.0f, r, 1.0f);
}

__device__ __forceinline__ unsigned long long pack2(float lo, float hi) {
    unsigned long long r;
    asm("mov.b64 %0, {%1, %2};" : "=l"(r) : "f"(lo), "f"(hi));
    return r;
}

// 64-dot: v in shared (broadcast LDS.128) vs 32 packed f32x2 pairs in regs.
__device__ __forceinline__ float dot64p(const float* v, const unsigned long long* w,
                                        unsigned long long bias_pk) {
    const ulonglong2* v2 = (const ulonglong2*)v;
    unsigned long long a0 = bias_pk, a1 = 0ULL, a2 = 0ULL, a3 = 0ULL;
    #pragma unroll
    for (int q = 0; q < 16; q += 2) {
        ulonglong2 va = v2[q];
        ulonglong2 vb = v2[q + 1];
        asm("fma.rn.f32x2 %0, %1, %2, %0;" : "+l"(a0) : "l"(va.x), "l"(w[2*q + 0]));
        asm("fma.rn.f32x2 %0, %1, %2, %0;" : "+l"(a1) : "l"(va.y), "l"(w[2*q + 1]));
        asm("fma.rn.f32x2 %0, %1, %2, %0;" : "+l"(a2) : "l"(vb.x), "l"(w[2*q + 2]));
        asm("fma.rn.f32x2 %0, %1, %2, %0;" : "+l"(a3) : "l"(vb.y), "l"(w[2*q + 3]));
    }
    asm("add.rn.f32x2 %0, %0, %1;" : "+l"(a0) : "l"(a1));
    asm("add.rn.f32x2 %0, %0, %1;" : "+l"(a2) : "l"(a3));
    asm("add.rn.f32x2 %0, %0, %1;" : "+l"(a0) : "l"(a2));
    float lo, hi;
    asm("mov.b64 {%0,%1}, %2;" : "=f"(lo), "=f"(hi) : "l"(a0));
    return lo + hi;
}

// 64-dot: shared vector vs 64 scalar float regs (front kernel).
__device__ __forceinline__ float mm64(const float* v, const float* w, float bias) {
    const float4* v4 = (const float4*)v;
    float a0 = 0.f, a1 = 0.f, a2 = 0.f, a3 = 0.f;
    #pragma unroll
    for (int q = 0; q < 16; q++) {
        float4 xv = v4[q];
        a0 = fmaf(xv.x, w[4 * q + 0], a0);
        a1 = fmaf(xv.y, w[4 * q + 1], a1);
        a2 = fmaf(xv.z, w[4 * q + 2], a2);
        a3 = fmaf(xv.w, w[4 * q + 3], a3);
    }
    return bias + ((a0 + a1) + (a2 + a3));
}

// ===================== Kernel A: encoder + attention + GRU partials =========
// grid: (NSL, Bc), block: 128. Each block: 12 t-values of one batch.
// Emits gp = W_ih @ (sum_t e^att h2[t]) and Se = sum_t e^att for its slice.
// (Unshifted softmax is safe: |att| is bounded by ||Wa2||_1, a few units.)
__global__ __launch_bounds__(128, 1)
void front_kernel(const float* __restrict__ x,
                  const float* __restrict__ W_s1, const float* __restrict__ b_s1,
                  const float* __restrict__ W_s2, const float* __restrict__ b_s2,
                  const float* __restrict__ Wa1,  const float* __restrict__ ba1,
                  const float* __restrict__ Wa2,  const float* __restrict__ W_ih)
{
    __shared__ __align__(16) float s_mx[TSLICE];
    __shared__ __align__(16) float s_h1[TSLICE][Hc];
    __shared__ __align__(16) float s_h2[TSLICE][Hc];
    __shared__ __align__(16) float s_P[Hc];
    __shared__ float s_att[TSLICE];
    __shared__ float s_e[TSLICE];

    const int tid = threadIdx.x;
    const int b   = blockIdx.y;
    const int sl  = blockIdx.x;
    const int t0  = sl * TSLICE;
    const float* xb = x + b * (Nc * Tc);

    // mean over nodes: 8 threads per t (16 nodes each) -> 96 = 3 FULL warps.
    if (tid < 8 * TSLICE) {
        int t = tid >> 3, q = tid & 7;
        const float* p = xb + t0 + t;
        float s = 0.f;
        #pragma unroll 8
        for (int n = q * 16; n < q * 16 + 16; n++) s += p[n * Tc];
        s += __shfl_xor_sync(0xffffffffu, s, 1);
        s += __shfl_xor_sync(0xffffffffu, s, 2);
        s += __shfl_xor_sync(0xffffffffu, s, 4);
        if (q == 0) s_mx[t] = s * (1.0f / Nc);
    }
    __syncthreads();

    {
        int k = tid & 63;
        float wk = W_s1[k], bk = b_s1[k];
        for (int t = tid >> 6; t < TSLICE; t += 2)
            s_h1[t][k] = fmaxf(fmaf(s_mx[t], wk, bk), 0.f);
    }
    __syncthreads();

    {
        int h = tid & 63;
        float wcol[Hc];
        #pragma unroll
        for (int k = 0; k < Hc; k++) wcol[k] = W_s2[k * Hc + h];
        float bias = b_s2[h];
        for (int t = tid >> 6; t < TSLICE; t += 2)
            s_h2[t][h] = fmaxf(mm64(s_h1[t], wcol, bias), 0.f);
    }
    if (tid < TSLICE) s_att[tid] = 0.f;
    __syncthreads();

    {
        int h = tid & 63;
        float wcol[Hc];
        #pragma unroll
        for (int k = 0; k < Hc; k++) wcol[k] = Wa1[k * Hc + h];
        float bias = ba1[h];
        float wa2  = Wa2[h];
        for (int t = tid >> 6; t < TSLICE; t += 2) {
            float v = ftanh(mm64(s_h2[t], wcol, bias)) * wa2;
            #pragma unroll
            for (int off = 16; off; off >>= 1) v += __shfl_xor_sync(0xffffffffu, v, off);
            if ((tid & 31) == 0) atomicAdd(&s_att[t], v);
        }
    }
    __syncthreads();

    // e[t] = exp(att[t]) (unshifted — bounded logits)
    if (tid < TSLICE) s_e[tid] = __expf(s_att[tid]);
    __syncthreads();

    // P[h] = sum_t e[t]*h2[t][h] (warps 0-1);  Se (warp 2)
    if (tid < Hc) {
        float acc = 0.f;
        #pragma unroll
        for (int t = 0; t < TSLICE; t++) acc = fmaf(s_e[t], s_h2[t][tid], acc);
        s_P[tid] = acc;
    } else if (tid < 96) {
        int lane = tid & 31;
        float v = (lane < TSLICE) ? s_e[lane] : 0.f;
        #pragma unroll
        for (int off = 16; off; off >>= 1) v += __shfl_xor_sync(0xffffffffu, v, off);
        if (lane == 0) g_Se[b * NSL + sl] = v;
    }
    __syncthreads();

    // gp[r] = W_ih[r] . P   (192 rows, 1-2 per thread; coalesced row loads)
    {
        float* gp = g_gp + (b * NSL + sl) * 3 * Hc;
        const float4* P4 = (const float4*)s_P;
        for (int r = tid; r < 3 * Hc; r += 128) {
            const float4* row = (const float4*)(W_ih + r * Hc);
            float a0 = 0.f, a1 = 0.f, a2 = 0.f, a3 = 0.f;
            #pragma unroll
            for (int q = 0; q < 16; q++) {
                float4 w4 = row[q];
                float4 v4 = P4[q];
                a0 = fmaf(w4.x, v4.x, a0);
                a1 = fmaf(w4.y, v4.y, a1);
                a2 = fmaf(w4.z, v4.z, a2);
                a3 = fmaf(w4.w, v4.w, a3);
            }
            gp[r] = (a0 + a1) + (a2 + a3);
        }
    }
}

// ============ Kernel B: gates + ODE + output, block = 64 ====================
__global__ __launch_bounds__(64, 1)
void ode_kernel(const float* __restrict__ b_ih, const float* __restrict__ b_hh,
                const float* __restrict__ W_o1, const float* __restrict__ b_o1,
                const float* __restrict__ W_o2, const float* __restrict__ b_o2,
                const float* __restrict__ W_out,const float* __restrict__ b_out,
                float* __restrict__ out)
{
    __shared__ __align__(16) float s_in[Hc], s_u[Hc];
    __shared__ __align__(16) float s_traj[TFc][Hc];
    __shared__ __align__(16) float s_wout[Hc];
    __shared__ __align__(16) float s_pred[TFc];

    const int tid = threadIdx.x;   // 0..63
    const int b   = blockIdx.x;
    const float bout = b_out[0];
    const int h = tid;

    s_wout[h] = W_out[h];

    // ODE weight packing FIRST: 128 independent coalesced LDGs go in flight
    // and overlap with the gate loads below.
    const float c = TANH_SCALE;
    unsigned long long w1p[32], w2p[32];
    #pragma unroll
    for (int j = 0; j < 32; j++) {
        w1p[j] = pack2(c * W_o1[(2 * j) * Hc + h], c * W_o1[(2 * j + 1) * Hc + h]);
        w2p[j] = pack2(c * W_o2[(2 * j) * Hc + h], c * W_o2[(2 * j + 1) * Hc + h]);
    }
    const unsigned long long b1p = pack2(c * b_o1[h], 0.f);
    const unsigned long long b2p = pack2(c * b_o2[h], 0.f);

    // gi[q*64+h] = (sum_sl gp[sl][q*64+h]) / (sum_sl Se[sl]) + b_ih[q*64+h]
    float yv;
    {
        const float* gpb = g_gp + b * NSL * 3 * Hc;
        const float* Seb = g_Se + b * NSL;
        float se = 0.f;
        #pragma unroll
        for (int s = 0; s < NSL; s++) se += Seb[s];
        float inv = __fdividef(1.f, se);

        float gi[3];
        #pragma unroll
        for (int q = 0; q < 3; q++) {
            float a = 0.f;
            #pragma unroll
            for (int s = 0; s < NSL; s++) a += gpb[s * 3 * Hc + q * Hc + h];
            gi[q] = fmaf(a, inv, b_ih[q * Hc + h]);
        }

        float r = fsigm(gi[0] + b_hh[h]);
        float z = fsigm(gi[1] + b_hh[Hc + h]);
        float n = ftanh(gi[2] + r * b_hh[2 * Hc + h]);
        yv = (1.f - z) * n;
    }
    s_in[h] = yv;
    s_traj[0][h] = yv;
    __syncthreads();

    const float dt    = 24.0f / 23.0f;
    const float third = 1.0f / 3.0f;

    for (int s = 1; s < TFc; s++) {
        float u, k1, k2, k3, k4;

        u = ftanh_z(dot64p(s_in, w1p, b1p)); s_u[h] = u; __syncthreads();
        k1 = ftanh_z(dot64p(s_u, w2p, b2p));
        s_in[h] = fmaf(dt * third, k1, yv); __syncthreads();

        u = ftanh_z(dot64p(s_in, w1p, b1p)); s_u[h] = u; __syncthreads();
        k2 = ftanh_z(dot64p(s_u, w2p, b2p));
        s_in[h] = yv + dt * (k2 - third * k1); __syncthreads();

        u = ftanh_z(dot64p(s_in, w1p, b1p)); s_u[h] = u; __syncthreads();
        k3 = ftanh_z(dot64p(s_u, w2p, b2p));
        s_in[h] = yv + dt * (k1 - k2 + k3); __syncthreads();

        u = ftanh_z(dot64p(s_in, w1p, b1p)); s_u[h] = u; __syncthreads();
        k4 = ftanh_z(dot64p(s_u, w2p, b2p));
        yv = yv + dt * 0.125f * (k1 + 3.f * (k2 + k3) + k4);
        s_in[h] = yv; s_traj[s][h] = yv; __syncthreads();
    }

    // predictions: pred[tf] = traj[tf] . W_out + b_out (2 warps)
    {
        int w = tid >> 5, lane = tid & 31;
        for (int tf = w; tf < TFc; tf += 2) {
            float v = s_traj[tf][lane] * s_wout[lane]
                    + s_traj[tf][lane + 32] * s_wout[lane + 32];
            #pragma unroll
            for (int off = 16; off; off >>= 1) v += __shfl_xor_sync(0xffffffffu, v, off);
            if (lane == 0) s_pred[tf] = v + bout;
        }
    }
    __syncthreads();

    // out[b][n][tf] = pred[tf] (node-constant), float4 stores
    {
        const float4* p4 = (const float4*)s_pred;     // 6 float4 per node row
        float4* ob4 = (float4*)(out + b * (Nc * TFc));
        #pragma unroll 4
        for (int i = tid; i < Nc * (TFc / 4); i += 64)
            ob4[i] = p4[i % (TFc / 4)];
    }
}

extern "C" void kernel_launch(void* const* d_in, const int* in_sizes, int n_in,
                              void* d_out, int out_size)
{
    const float* x     = (const float*)d_in[0];
    const float* W_s1  = (const float*)d_in[1];
    const float* b_s1  = (const float*)d_in[2];
    const float* W_s2  = (const float*)d_in[3];
    const float* b_s2  = (const float*)d_in[4];
    const float* Wa1   = (const float*)d_in[5];
    const float* ba1   = (const float*)d_in[6];
    const float* Wa2   = (const float*)d_in[7];
    const float* W_ih  = (const float*)d_in[9];
    const float* b_ih  = (const float*)d_in[11];
    const float* b_hh  = (const float*)d_in[12];
    const float* W_o1  = (const float*)d_in[13];
    const float* b_o1  = (const float*)d_in[14];
    const float* W_o2  = (const float*)d_in[15];
    const float* b_o2  = (const float*)d_in[16];
    const float* W_out = (const float*)d_in[17];
    const float* b_out = (const float*)d_in[18];

    dim3 gridA(NSL, Bc);
    front_kernel<<<gridA, 128>>>(x, W_s1, b_s1, W_s2, b_s2, Wa1, ba1, Wa2, W_ih);
    ode_kernel<<<Bc, 64>>>(b_ih, b_hh,
                           W_o1, b_o1, W_o2, b_o2,
                           W_out, b_out, (float*)d_out);
}